// round 12
// baseline (speedup 1.0000x reference)
#include <cuda_runtime.h>
#include <cuda_fp16.h>
#include <stdint.h>
#include <math.h>

// ---------------- problem constants ----------------
#define T_TOKENS 8192          // 4 * 2048
#define DD 1024                // emb dim
#define HH 4096                // hidden dim
#define EE 8                   // experts
#define PAIRS (T_TOKENS * 2)   // 16384 routed (token, expert) pairs

// ---------------- device scratch: proven footprint; NO weight copies ----------
__device__ int   g_count[EE];
__device__ int   g_offset[EE];
__device__ int   g_ek[PAIRS];
__device__ int   g_slot[PAIRS];
__device__ float g_gate[PAIRS];
__device__ int   g_row[PAIRS];
__device__ int   g_tok[PAIRS];
__device__ float g_hid[(size_t)PAIRS * HH];     // head 134 MB used as fp16 hid
__device__ float g_y  [(size_t)PAIRS * DD];     // head 16.7 MB = x fp16 alias

#define HID_H   (reinterpret_cast<__half*>(g_hid))
#define XH      (reinterpret_cast<__half*>(g_y))

// ---------------- helpers ----------------
__device__ __forceinline__ uint32_t smem_u32(const void* p) {
    uint32_t a;
    asm("{ .reg .u64 t; cvta.to.shared.u64 t, %1; cvt.u32.u64 %0, t; }" : "=r"(a) : "l"(p));
    return a;
}
__device__ __forceinline__ void cp_async16(uint32_t dst, const void* src) {
    asm volatile("cp.async.cg.shared.global [%0], [%1], 16;" :: "r"(dst), "l"(src));
}
__device__ __forceinline__ void cp_commit() {
    asm volatile("cp.async.commit_group;" ::: "memory");
}
template <int N>
__device__ __forceinline__ void cp_wait() {
    asm volatile("cp.async.wait_group %0;" :: "n"(N) : "memory");
}
__device__ __forceinline__ uint32_t pack_h2(float lo, float hi) {
    __half2 h = __floats2half2_rn(lo, hi);      // low 16 bits = lo
    return *reinterpret_cast<uint32_t*>(&h);
}
__device__ __forceinline__ void mma_f16(float* d, const uint32_t* a, const uint32_t* b) {
    asm volatile(
        "mma.sync.aligned.m16n8k16.row.col.f32.f16.f16.f32 "
        "{%0,%1,%2,%3}, {%4,%5,%6,%7}, {%8,%9}, {%0,%1,%2,%3};"
        : "+f"(d[0]), "+f"(d[1]), "+f"(d[2]), "+f"(d[3])
        : "r"(a[0]), "r"(a[1]), "r"(a[2]), "r"(a[3]), "r"(b[0]), "r"(b[1]));
}

// ---------------- kernel 0: zero counters ----------------
__global__ void zero_counts_kernel() {
    if (threadIdx.x < EE) g_count[threadIdx.x] = 0;
}

// ---------------- kernel 1: router (1 warp/token) + fused x->fp16 ------------
__global__ void router_kernel(const float* __restrict__ x,
                              const float* __restrict__ wr,
                              const float* __restrict__ br) {
    int warp = (blockIdx.x * blockDim.x + threadIdx.x) >> 5;
    int lane = threadIdx.x & 31;
    if (warp >= T_TOKENS) return;
    const float* xr = x + (size_t)warp * DD;
    __half* xh = XH + (size_t)warp * DD;

    float acc[EE];
#pragma unroll
    for (int e = 0; e < EE; e++) acc[e] = 0.f;
#pragma unroll 4
    for (int c = 0; c < DD / 32; c++) {
        int k = c * 32 + lane;
        float xv = __ldg(xr + k);
        xh[k] = __float2half_rn(xv);             // fused fp16 conversion
        const float4* w4 = reinterpret_cast<const float4*>(wr + (size_t)k * EE);
        float4 a = __ldg(&w4[0]);
        float4 b = __ldg(&w4[1]);
        acc[0] += xv * a.x; acc[1] += xv * a.y; acc[2] += xv * a.z; acc[3] += xv * a.w;
        acc[4] += xv * b.x; acc[5] += xv * b.y; acc[6] += xv * b.z; acc[7] += xv * b.w;
    }
#pragma unroll
    for (int e = 0; e < EE; e++)
#pragma unroll
        for (int o = 16; o > 0; o >>= 1)
            acc[e] += __shfl_down_sync(0xffffffffu, acc[e], o);

    if (lane == 0) {
        float l[EE];
        float mx = -1e30f;
#pragma unroll
        for (int e = 0; e < EE; e++) { l[e] = acc[e] + br[e]; mx = fmaxf(mx, l[e]); }
        float s = 0.f;
#pragma unroll
        for (int e = 0; e < EE; e++) { l[e] = expf(l[e] - mx); s += l[e]; }
        float inv = 1.0f / s;
        int e0 = 0;
#pragma unroll
        for (int e = 1; e < EE; e++) if (l[e] > l[e0]) e0 = e;
        int e1 = (e0 == 0) ? 1 : 0;
#pragma unroll
        for (int e = 0; e < EE; e++) if (e != e0 && l[e] > l[e1]) e1 = e;
        int t = warp;
        int s0 = atomicAdd(&g_count[e0], 1);
        g_ek[t * 2 + 0] = e0; g_slot[t * 2 + 0] = s0; g_gate[t * 2 + 0] = l[e0] * inv;
        int s1 = atomicAdd(&g_count[e1], 1);
        g_ek[t * 2 + 1] = e1; g_slot[t * 2 + 1] = s1; g_gate[t * 2 + 1] = l[e1] * inv;
    }
}

// ---------------- kernel 2: prefix offsets ----------------
__global__ void offsets_kernel() {
    if (threadIdx.x == 0 && blockIdx.x == 0) {
        int s = 0;
#pragma unroll
        for (int e = 0; e < EE; e++) { g_offset[e] = s; s += g_count[e]; }
    }
}

// ---------------- kernel 3: scatter compact rows ----------------
__global__ void scatter_kernel() {
    int i = blockIdx.x * blockDim.x + threadIdx.x;
    if (i >= PAIRS) return;
    int e = g_ek[i];
    int row = g_offset[e] + g_slot[i];
    g_row[i] = row;
    g_tok[row] = i >> 1;
}

// ---------------- grouped GEMM: m16n8k16 fp16, 64x64 warp tiles --------------
// CTA tile 128x256x32; 8 warps (2m x 4n) of 64x64; occupancy 1 (128 accums).
// A fp16 via cp.async (XH / HID_H). B: LDG fp32 from HARNESS weights in two
// batches interleaved with the two k=16 MMA blocks, packed to half2, STS.
constexpr int BM = 128, BN = 256, BK = 32;   // BK in k-elements
constexpr int A_STR_U = 20;                  // 40 fp16 = 80 B row stride
constexpr int B_STR_U = 264;                 // u32 stride per k-pair row (256+8)
constexpr int A_TILE_U = BM * A_STR_U;       // 2560 u32
constexpr int B_TILE_U = (BK / 2) * B_STR_U; // 4224 u32
constexpr int STAGE_U  = A_TILE_U + B_TILE_U;
constexpr int GEMM_SMEM = 2 * STAGE_U * 4;   // 54272 bytes

template <int NN, int KK, bool FFN1>
__global__ void __launch_bounds__(256, 1)
moe_gemm_h(const float* __restrict__ W_all,      // harness fp32 [E][K][N]
           const float* __restrict__ bias_all) {
    constexpr int NCH = KK / BK;
    extern __shared__ uint32_t smu[];
    uint32_t sb = smem_u32(smu);

    int e = blockIdx.z;
    int cnt = g_count[e];
    int m0 = blockIdx.y * BM;
    if (m0 >= cnt) return;
    int off = g_offset[e];
    int n0 = blockIdx.x * BN;

    const float* W    = W_all + (size_t)e * KK * NN;
    const float* bias = bias_all + (size_t)e * NN;

    int tid = threadIdx.x;
    int wid = tid >> 5, lane = tid & 31;
    int wm = wid >> 2, wn = wid & 3;        // 2 x 4 warps; warp tile 64(m) x 64(n)
    int g = lane >> 2, tg = lane & 3;

    // ---- A: 2 gathered fp16 row pointers per thread ----
    const __half* asrc[2];
#pragma unroll
    for (int i = 0; i < 2; i++) {
        int r = i * 64 + (tid >> 2);
        int gm = m0 + r;
        if (gm > cnt - 1) gm = cnt - 1;     // clamp; masked in epilogue
        int grow = off + gm;
        const __half* base = FFN1 ? (XH + (size_t)g_tok[grow] * KK)
                                  : (HID_H + (size_t)grow * KK);
        asrc[i] = base + (tid & 3) * 8;
    }
    uint32_t adst0 = sb + (uint32_t)((tid >> 2) * 80 + (tid & 3) * 16);
    constexpr uint32_t STAGE_B = STAGE_U * 4;

    // ---- B mapping: kpair row kp = tid/16 (16 rows); base col = (tid%16)*4,
    //      4 segments 64 u32 apart cover 256 cols ----
    int bkp = tid >> 4;
    int bn  = (tid & 15) * 4;
    const float* bw0 = W + (size_t)(2 * bkp)     * NN + n0 + bn;
    const float* bw1 = W + (size_t)(2 * bkp + 1) * NN + n0 + bn;
    uint32_t bst_off = (uint32_t)(A_TILE_U + bkp * B_STR_U + bn);

    float acc[4][8][4];
#pragma unroll
    for (int mi = 0; mi < 4; mi++)
#pragma unroll
        for (int ni = 0; ni < 8; ni++)
#pragma unroll
            for (int q = 0; q < 4; q++) acc[mi][ni][q] = 0.f;

    // ---- prologue: fill stage 0 ----
#pragma unroll
    for (int i = 0; i < 2; i++) cp_async16(adst0 + i * (64 * 80), asrc[i]);
    cp_commit();
#pragma unroll
    for (int s = 0; s < 4; s++) {
        float4 a0 = *reinterpret_cast<const float4*>(bw0 + s * 64);
        float4 a1 = *reinterpret_cast<const float4*>(bw1 + s * 64);
        *reinterpret_cast<uint4*>(smu + bst_off + s * 64) =
            make_uint4(pack_h2(a0.x, a1.x), pack_h2(a0.y, a1.y),
                       pack_h2(a0.z, a1.z), pack_h2(a0.w, a1.w));
    }
    cp_wait<0>();
    __syncthreads();

#pragma unroll 1
    for (int c = 0; c < NCH; c++) {
        float4 s0a, s0b, s1a, s1b;               // 16 staging regs, reused
        bool pf = (c + 1 < NCH);
        uint32_t so = ((c + 1) & 1) * STAGE_B;
        uint32_t* bst = smu + ((c + 1) & 1) * STAGE_U + bst_off;
        size_t brow = (size_t)(c + 1) * BK * NN;
        if (pf) {
            int ka = (c + 1) * BK;
#pragma unroll
            for (int i = 0; i < 2; i++)
                cp_async16(adst0 + so + i * (64 * 80), asrc[i] + ka);
            cp_commit();
            s0a = *reinterpret_cast<const float4*>(bw0 + brow);        // seg 0
            s0b = *reinterpret_cast<const float4*>(bw1 + brow);
            s1a = *reinterpret_cast<const float4*>(bw0 + brow + 64);   // seg 1
            s1b = *reinterpret_cast<const float4*>(bw1 + brow + 64);
        }

        const uint32_t* As = smu + (c & 1) * STAGE_U;
        const uint32_t* Bs = As + A_TILE_U;

        // ---- kh = 0 ----
        {
            uint32_t af[4][4], bf[8][2];
#pragma unroll
            for (int mi = 0; mi < 4; mi++) {
                const uint32_t* ap = As + (wm * 64 + mi * 16 + g) * A_STR_U + tg;
                af[mi][0] = ap[0];
                af[mi][1] = ap[8 * A_STR_U];
                af[mi][2] = ap[4];
                af[mi][3] = ap[8 * A_STR_U + 4];
            }
#pragma unroll
            for (int ni = 0; ni < 8; ni++) {
                const uint32_t* bp = Bs + tg * B_STR_U + wn * 64 + ni * 8 + g;
                bf[ni][0] = bp[0];
                bf[ni][1] = bp[4 * B_STR_U];
            }
#pragma unroll
            for (int mi = 0; mi < 4; mi++)
#pragma unroll
                for (int ni = 0; ni < 8; ni++)
                    mma_f16(acc[mi][ni], af[mi], bf[ni]);
        }

        if (pf) {                                // STS batch0, LDG batch1
            *reinterpret_cast<uint4*>(bst) =
                make_uint4(pack_h2(s0a.x, s0b.x), pack_h2(s0a.y, s0b.y),
                           pack_h2(s0a.z, s0b.z), pack_h2(s0a.w, s0b.w));
            *reinterpret_cast<uint4*>(bst + 64) =
                make_uint4(pack_h2(s1a.x, s1b.x), pack_h2(s1a.y, s1b.y),
                           pack_h2(s1a.z, s1b.z), pack_h2(s1a.w, s1b.w));
            s0a = *reinterpret_cast<const float4*>(bw0 + brow + 128);  // seg 2
            s0b = *reinterpret_cast<const float4*>(bw1 + brow + 128);
            s1a = *reinterpret_cast<const float4*>(bw0 + brow + 192);  // seg 3
            s1b = *reinterpret_cast<const float4*>(bw1 + brow + 192);
        }

        // ---- kh = 1 ----
        {
            uint32_t af[4][4], bf[8][2];
#pragma unroll
            for (int mi = 0; mi < 4; mi++) {
                const uint32_t* ap = As + (wm * 64 + mi * 16 + g) * A_STR_U + 8 + tg;
                af[mi][0] = ap[0];
                af[mi][1] = ap[8 * A_STR_U];
                af[mi][2] = ap[4];
                af[mi][3] = ap[8 * A_STR_U + 4];
            }
#pragma unroll
            for (int ni = 0; ni < 8; ni++) {
                const uint32_t* bp = Bs + (8 + tg) * B_STR_U + wn * 64 + ni * 8 + g;
                bf[ni][0] = bp[0];
                bf[ni][1] = bp[4 * B_STR_U];
            }
#pragma unroll
            for (int mi = 0; mi < 4; mi++)
#pragma unroll
                for (int ni = 0; ni < 8; ni++)
                    mma_f16(acc[mi][ni], af[mi], bf[ni]);
        }

        if (pf) {                                // STS batch1
            *reinterpret_cast<uint4*>(bst + 128) =
                make_uint4(pack_h2(s0a.x, s0b.x), pack_h2(s0a.y, s0b.y),
                           pack_h2(s0a.z, s0b.z), pack_h2(s0a.w, s0b.w));
            *reinterpret_cast<uint4*>(bst + 192) =
                make_uint4(pack_h2(s1a.x, s1b.x), pack_h2(s1a.y, s1b.y),
                           pack_h2(s1a.z, s1b.z), pack_h2(s1a.w, s1b.w));
            cp_wait<0>();
        }
        __syncthreads();
    }

    // ---- epilogue ----
#pragma unroll
    for (int mi = 0; mi < 4; mi++) {
        int r0 = m0 + wm * 64 + mi * 16 + g;
        int r1 = r0 + 8;
        bool va = r0 < cnt, vb = r1 < cnt;
        size_t row0 = (size_t)(off + r0), row1 = (size_t)(off + r1);
#pragma unroll
        for (int ni = 0; ni < 8; ni++) {
            int col = wn * 64 + ni * 8 + 2 * tg;
            float2 bv = *reinterpret_cast<const float2*>(bias + n0 + col);
            float c00 = acc[mi][ni][0] + bv.x;
            float c01 = acc[mi][ni][1] + bv.y;
            float c10 = acc[mi][ni][2] + bv.x;
            float c11 = acc[mi][ni][3] + bv.y;
            if (FFN1) {
                uint32_t h0 = pack_h2(fmaxf(c00, 0.f), fmaxf(c01, 0.f));
                uint32_t h1 = pack_h2(fmaxf(c10, 0.f), fmaxf(c11, 0.f));
                if (va) *reinterpret_cast<uint32_t*>(
                            HID_H + row0 * NN + n0 + col) = h0;
                if (vb) *reinterpret_cast<uint32_t*>(
                            HID_H + row1 * NN + n0 + col) = h1;
            } else {
                if (va) *reinterpret_cast<float2*>(
                            g_y + row0 * NN + n0 + col) = make_float2(c00, c01);
                if (vb) *reinterpret_cast<float2*>(
                            g_y + row1 * NN + n0 + col) = make_float2(c10, c11);
            }
        }
    }
}

// ---------------- combine pairs into output ----------------
__global__ void combine_kernel(float* __restrict__ out) {
    int i = blockIdx.x * blockDim.x + threadIdx.x;
    if (i >= T_TOKENS * (DD / 4)) return;
    int t  = i / (DD / 4);
    int d4 = i % (DD / 4);
    int r0 = g_row[t * 2 + 0];
    int r1 = g_row[t * 2 + 1];
    float g0 = g_gate[t * 2 + 0];
    float g1 = g_gate[t * 2 + 1];
    const float4* y0 = reinterpret_cast<const float4*>(g_y + (size_t)r0 * DD);
    const float4* y1 = reinterpret_cast<const float4*>(g_y + (size_t)r1 * DD);
    float4 a = y0[d4], b = y1[d4], o;
    o.x = g0 * a.x + g1 * b.x;
    o.y = g0 * a.y + g1 * b.y;
    o.z = g0 * a.z + g1 * b.z;
    o.w = g0 * a.w + g1 * b.w;
    reinterpret_cast<float4*>(out)[i] = o;
}

// ---------------- launch ----------------
extern "C" void kernel_launch(void* const* d_in, const int* in_sizes, int n_in,
                              void* d_out, int out_size) {
    const float* x  = (const float*)d_in[0];
    const float* wr = (const float*)d_in[1];
    const float* br = (const float*)d_in[2];
    const float* w1 = (const float*)d_in[3];
    const float* b1 = (const float*)d_in[4];
    const float* w2 = (const float*)d_in[5];
    const float* b2 = (const float*)d_in[6];
    float* out = (float*)d_out;

    cudaFuncSetAttribute(moe_gemm_h<HH, DD, true>,
                         cudaFuncAttributeMaxDynamicSharedMemorySize, GEMM_SMEM);
    cudaFuncSetAttribute(moe_gemm_h<DD, HH, false>,
                         cudaFuncAttributeMaxDynamicSharedMemorySize, GEMM_SMEM);

    zero_counts_kernel<<<1, 32>>>();
    router_kernel<<<T_TOKENS / 8, 256>>>(x, wr, br);   // also writes x fp16
    offsets_kernel<<<1, 32>>>();
    scatter_kernel<<<PAIRS / 256, 256>>>();

    // FFN1: N=4096, K=1024 (B from harness w1, converted in-kernel)
    {
        dim3 grid(HH / BN, 8192 / BM, EE);
        moe_gemm_h<HH, DD, true><<<grid, 256, GEMM_SMEM>>>(w1, b1);
    }
    // FFN2: N=1024, K=4096 (B from harness w2)
    {
        dim3 grid(DD / BN, 8192 / BM, EE);
        moe_gemm_h<DD, HH, false><<<grid, 256, GEMM_SMEM>>>(w2, b2);
    }

    combine_kernel<<<(T_TOKENS * (DD / 4)) / 256, 256>>>(out);
}

// round 13
// speedup vs baseline: 1.0794x; 1.0794x over previous
#include <cuda_runtime.h>
#include <cuda_fp16.h>
#include <stdint.h>
#include <math.h>

// ---------------- problem constants ----------------
#define T_TOKENS 8192          // 4 * 2048
#define DD 1024                // emb dim
#define HH 4096                // hidden dim
#define EE 8                   // experts
#define PAIRS (T_TOKENS * 2)   // 16384 routed (token, expert) pairs

// ---------------- device scratch: byte-identical proven footprint -------------
__device__ int   g_count[EE];
__device__ int   g_offset[EE];
__device__ int   g_ek[PAIRS];
__device__ int   g_slot[PAIRS];
__device__ float g_gate[PAIRS];
__device__ int   g_row[PAIRS];     // repurposed: per compact row, gate as bits
__device__ int   g_tok[PAIRS];     // per compact row: token id
__device__ float g_hid[(size_t)PAIRS * HH];     // head 134 MB used as fp16 hid
__device__ float g_y  [(size_t)PAIRS * DD];     // head 16.7 MB = x fp16 alias

#define HID_H   (reinterpret_cast<__half*>(g_hid))
#define XH      (reinterpret_cast<__half*>(g_y))

// ---------------- helpers ----------------
__device__ __forceinline__ uint32_t smem_u32(const void* p) {
    uint32_t a;
    asm("{ .reg .u64 t; cvta.to.shared.u64 t, %1; cvt.u32.u64 %0, t; }" : "=r"(a) : "l"(p));
    return a;
}
__device__ __forceinline__ void cp_async16(uint32_t dst, const void* src) {
    asm volatile("cp.async.cg.shared.global [%0], [%1], 16;" :: "r"(dst), "l"(src));
}
__device__ __forceinline__ void cp_commit() {
    asm volatile("cp.async.commit_group;" ::: "memory");
}
template <int N>
__device__ __forceinline__ void cp_wait() {
    asm volatile("cp.async.wait_group %0;" :: "n"(N) : "memory");
}
__device__ __forceinline__ uint32_t pack_h2(float lo, float hi) {
    __half2 h = __floats2half2_rn(lo, hi);      // low 16 bits = lo
    return *reinterpret_cast<uint32_t*>(&h);
}
__device__ __forceinline__ void mma_f16(float* d, const uint32_t* a, const uint32_t* b) {
    asm volatile(
        "mma.sync.aligned.m16n8k16.row.col.f32.f16.f16.f32 "
        "{%0,%1,%2,%3}, {%4,%5,%6,%7}, {%8,%9}, {%0,%1,%2,%3};"
        : "+f"(d[0]), "+f"(d[1]), "+f"(d[2]), "+f"(d[3])
        : "r"(a[0]), "r"(a[1]), "r"(a[2]), "r"(a[3]), "r"(b[0]), "r"(b[1]));
}

// ---------------- kernel 0: zero counters ----------------
__global__ void zero_counts_kernel() {
    if (threadIdx.x < EE) g_count[threadIdx.x] = 0;
}

// ---------------- kernel: zero the output (atomicAdd target) ----------------
__global__ void zero_out_kernel(float4* __restrict__ out) {
    int i = blockIdx.x * blockDim.x + threadIdx.x;
    out[i] = make_float4(0.f, 0.f, 0.f, 0.f);
}

// ---------------- kernel 1: router (1 warp/token) + fused x->fp16 ------------
__global__ void router_kernel(const float* __restrict__ x,
                              const float* __restrict__ wr,
                              const float* __restrict__ br) {
    int warp = (blockIdx.x * blockDim.x + threadIdx.x) >> 5;
    int lane = threadIdx.x & 31;
    if (warp >= T_TOKENS) return;
    const float* xr = x + (size_t)warp * DD;
    __half* xh = XH + (size_t)warp * DD;

    float acc[EE];
#pragma unroll
    for (int e = 0; e < EE; e++) acc[e] = 0.f;
#pragma unroll 4
    for (int c = 0; c < DD / 32; c++) {
        int k = c * 32 + lane;
        float xv = __ldg(xr + k);
        xh[k] = __float2half_rn(xv);             // fused fp16 conversion
        const float4* w4 = reinterpret_cast<const float4*>(wr + (size_t)k * EE);
        float4 a = __ldg(&w4[0]);
        float4 b = __ldg(&w4[1]);
        acc[0] += xv * a.x; acc[1] += xv * a.y; acc[2] += xv * a.z; acc[3] += xv * a.w;
        acc[4] += xv * b.x; acc[5] += xv * b.y; acc[6] += xv * b.z; acc[7] += xv * b.w;
    }
#pragma unroll
    for (int e = 0; e < EE; e++)
#pragma unroll
        for (int o = 16; o > 0; o >>= 1)
            acc[e] += __shfl_down_sync(0xffffffffu, acc[e], o);

    if (lane == 0) {
        float l[EE];
        float mx = -1e30f;
#pragma unroll
        for (int e = 0; e < EE; e++) { l[e] = acc[e] + br[e]; mx = fmaxf(mx, l[e]); }
        float s = 0.f;
#pragma unroll
        for (int e = 0; e < EE; e++) { l[e] = expf(l[e] - mx); s += l[e]; }
        float inv = 1.0f / s;
        int e0 = 0;
#pragma unroll
        for (int e = 1; e < EE; e++) if (l[e] > l[e0]) e0 = e;
        int e1 = (e0 == 0) ? 1 : 0;
#pragma unroll
        for (int e = 0; e < EE; e++) if (e != e0 && l[e] > l[e1]) e1 = e;
        int t = warp;
        int s0 = atomicAdd(&g_count[e0], 1);
        g_ek[t * 2 + 0] = e0; g_slot[t * 2 + 0] = s0; g_gate[t * 2 + 0] = l[e0] * inv;
        int s1 = atomicAdd(&g_count[e1], 1);
        g_ek[t * 2 + 1] = e1; g_slot[t * 2 + 1] = s1; g_gate[t * 2 + 1] = l[e1] * inv;
    }
}

// ---------------- kernel 2: prefix offsets ----------------
__global__ void offsets_kernel() {
    if (threadIdx.x == 0 && blockIdx.x == 0) {
        int s = 0;
#pragma unroll
        for (int e = 0; e < EE; e++) { g_offset[e] = s; s += g_count[e]; }
    }
}

// ---------------- kernel 3: scatter compact rows (row -> token, gate) --------
__global__ void scatter_kernel() {
    int i = blockIdx.x * blockDim.x + threadIdx.x;
    if (i >= PAIRS) return;
    int e = g_ek[i];
    int row = g_offset[e] + g_slot[i];
    g_tok[row] = i >> 1;                           // token id
    g_row[row] = __float_as_int(g_gate[i]);        // gate bits, row-indexed
}

// ---------------- grouped GEMM: m16n8k16 fp16, BK=64, occ 2 ------------------
// CTA 128x128x64; 8 warps (2m x 4n) of 64x32. A fp16 cp.async (XH / HID_H).
// B: LDG fp32 from HARNESS weights in two batches interleaved with the four
// k=16 MMA blocks, packed to half2, STS. FFN2 fuses gate*val atomicAdd to out.
constexpr int BM = 128, BN = 128, BK = 64;   // BK in k-elements
constexpr int A_STR_U = 36;                  // 72 fp16 = 144 B row stride
constexpr int B_STR_U = 136;                 // u32 stride per k-pair row
constexpr int A_TILE_U = BM * A_STR_U;       // 4608 u32
constexpr int B_TILE_U = (BK / 2) * B_STR_U; // 4352 u32
constexpr int STAGE_U  = A_TILE_U + B_TILE_U;
constexpr int GEMM_SMEM = 2 * STAGE_U * 4;   // 71680 bytes

template <int NN, int KK, bool FFN1>
__global__ void __launch_bounds__(256, 2)
moe_gemm_h(const float* __restrict__ W_all,      // harness fp32 [E][K][N]
           const float* __restrict__ bias_all,
           float* __restrict__ out) {            // used by FFN2 only
    constexpr int NCH = KK / BK;
    extern __shared__ uint32_t smu[];
    uint32_t sb = smem_u32(smu);

    int e = blockIdx.z;
    int cnt = g_count[e];
    int m0 = blockIdx.y * BM;
    if (m0 >= cnt) return;
    int off = g_offset[e];
    int n0 = blockIdx.x * BN;

    const float* W    = W_all + (size_t)e * KK * NN;
    const float* bias = bias_all + (size_t)e * NN;

    int tid = threadIdx.x;
    int wid = tid >> 5, lane = tid & 31;
    int wm = wid >> 2, wn = wid & 3;        // 2 x 4 warps; warp tile 64(m) x 32(n)
    int g = lane >> 2, tg = lane & 3;

    // ---- A: ONE gathered fp16 row pointer per thread (row = tid/2) ----
    const __half* asrc;
    {
        int r = tid >> 1;
        int gm = m0 + r;
        if (gm > cnt - 1) gm = cnt - 1;     // clamp; masked in epilogue
        int grow = off + gm;
        const __half* base = FFN1 ? (XH + (size_t)g_tok[grow] * KK)
                                  : (HID_H + (size_t)grow * KK);
        asrc = base + (tid & 1) * 32;       // half-row: 32 fp16 = 64 B
    }
    uint32_t adst0 = sb + (uint32_t)((tid >> 1) * 144 + (tid & 1) * 64);
    constexpr uint32_t STAGE_B = STAGE_U * 4;

    // ---- B mapping: kpair rows kp = tid/16 and kp+16; cols (tid%16)*4 + {0,64}
    int bkp = tid >> 4;
    int bn  = (tid & 15) * 4;
    const float* bw0 = W + (size_t)(2 * bkp)     * NN + n0 + bn;
    const float* bw1 = W + (size_t)(2 * bkp + 1) * NN + n0 + bn;
    uint32_t bst_off = (uint32_t)(A_TILE_U + bkp * B_STR_U + bn);

    float acc[4][4][4];
#pragma unroll
    for (int mi = 0; mi < 4; mi++)
#pragma unroll
        for (int ni = 0; ni < 4; ni++)
#pragma unroll
            for (int q = 0; q < 4; q++) acc[mi][ni][q] = 0.f;

    // ---- prologue: fill stage 0 ----
#pragma unroll
    for (int q = 0; q < 4; q++) cp_async16(adst0 + q * 16, asrc + q * 8);
    cp_commit();
#pragma unroll
    for (int b = 0; b < 2; b++) {           // kp group b: rows bkp + 16b
        size_t ro = (size_t)(32 * b) * NN;
#pragma unroll
        for (int s = 0; s < 2; s++) {       // n segment s: +64s
            float4 a0 = *reinterpret_cast<const float4*>(bw0 + ro + s * 64);
            float4 a1 = *reinterpret_cast<const float4*>(bw1 + ro + s * 64);
            *reinterpret_cast<uint4*>(smu + bst_off + b * (16 * B_STR_U) + s * 64) =
                make_uint4(pack_h2(a0.x, a1.x), pack_h2(a0.y, a1.y),
                           pack_h2(a0.z, a1.z), pack_h2(a0.w, a1.w));
        }
    }
    cp_wait<0>();
    __syncthreads();

#pragma unroll 1
    for (int c = 0; c < NCH; c++) {
        float4 s0a, s0b, s1a, s1b;          // 16 staging regs, reused per batch
        bool pf = (c + 1 < NCH);
        uint32_t so = ((c + 1) & 1) * STAGE_B;
        uint32_t* bst = smu + ((c + 1) & 1) * STAGE_U + bst_off;
        size_t brow = (size_t)(c + 1) * BK * NN;
        if (pf) {
            int ka = (c + 1) * BK;
#pragma unroll
            for (int q = 0; q < 4; q++)
                cp_async16(adst0 + so + q * 16, asrc + ka + q * 8);
            cp_commit();
            s0a = *reinterpret_cast<const float4*>(bw0 + brow);        // batch0
            s0b = *reinterpret_cast<const float4*>(bw1 + brow);
            s1a = *reinterpret_cast<const float4*>(bw0 + brow + 64);
            s1b = *reinterpret_cast<const float4*>(bw1 + brow + 64);
        }

        const uint32_t* As = smu + (c & 1) * STAGE_U;
        const uint32_t* Bs = As + A_TILE_U;

#pragma unroll
        for (int kh = 0; kh < 4; kh++) {    // four k=16 steps per BK=64
            uint32_t af[4][4], bf[4][2];
#pragma unroll
            for (int mi = 0; mi < 4; mi++) {
                const uint32_t* ap = As + (wm * 64 + mi * 16 + g) * A_STR_U + kh * 8 + tg;
                af[mi][0] = ap[0];
                af[mi][1] = ap[8 * A_STR_U];
                af[mi][2] = ap[4];
                af[mi][3] = ap[8 * A_STR_U + 4];
            }
#pragma unroll
            for (int ni = 0; ni < 4; ni++) {
                const uint32_t* bp = Bs + (kh * 8 + tg) * B_STR_U + wn * 32 + ni * 8 + g;
                bf[ni][0] = bp[0];
                bf[ni][1] = bp[4 * B_STR_U];
            }
#pragma unroll
            for (int mi = 0; mi < 4; mi++)
#pragma unroll
                for (int ni = 0; ni < 4; ni++)
                    mma_f16(acc[mi][ni], af[mi], bf[ni]);

            if (kh == 0 && pf) {            // STS batch0, LDG batch1
                *reinterpret_cast<uint4*>(bst) =
                    make_uint4(pack_h2(s0a.x, s0b.x), pack_h2(s0a.y, s0b.y),
                               pack_h2(s0a.z, s0b.z), pack_h2(s0a.w, s0b.w));
                *reinterpret_cast<uint4*>(bst + 64) =
                    make_uint4(pack_h2(s1a.x, s1b.x), pack_h2(s1a.y, s1b.y),
                               pack_h2(s1a.z, s1b.z), pack_h2(s1a.w, s1b.w));
                s0a = *reinterpret_cast<const float4*>(bw0 + brow + (size_t)32 * NN);
                s0b = *reinterpret_cast<const float4*>(bw1 + brow + (size_t)32 * NN);
                s1a = *reinterpret_cast<const float4*>(bw0 + brow + (size_t)32 * NN + 64);
                s1b = *reinterpret_cast<const float4*>(bw1 + brow + (size_t)32 * NN + 64);
            }
            if (kh == 2 && pf) {            // STS batch1
                *reinterpret_cast<uint4*>(bst + 16 * B_STR_U) =
                    make_uint4(pack_h2(s0a.x, s0b.x), pack_h2(s0a.y, s0b.y),
                               pack_h2(s0a.z, s0b.z), pack_h2(s0a.w, s0b.w));
                *reinterpret_cast<uint4*>(bst + 16 * B_STR_U + 64) =
                    make_uint4(pack_h2(s1a.x, s1b.x), pack_h2(s1a.y, s1b.y),
                               pack_h2(s1a.z, s1b.z), pack_h2(s1a.w, s1b.w));
            }
        }
        cp_wait<0>();
        __syncthreads();
    }

    // ---- epilogue ----
#pragma unroll
    for (int mi = 0; mi < 4; mi++) {
        int r0 = m0 + wm * 64 + mi * 16 + g;
        int r1 = r0 + 8;
        bool va = r0 < cnt, vb = r1 < cnt;
        size_t row0 = (size_t)(off + r0), row1 = (size_t)(off + r1);
        if (FFN1) {
#pragma unroll
            for (int ni = 0; ni < 4; ni++) {
                int col = ni * 8 + 2 * tg;
                float2 bv = *reinterpret_cast<const float2*>(bias + n0 + wn * 32 + col);
                uint32_t h0 = pack_h2(fmaxf(acc[mi][ni][0] + bv.x, 0.f),
                                      fmaxf(acc[mi][ni][1] + bv.y, 0.f));
                uint32_t h1 = pack_h2(fmaxf(acc[mi][ni][2] + bv.x, 0.f),
                                      fmaxf(acc[mi][ni][3] + bv.y, 0.f));
                if (va) *reinterpret_cast<uint32_t*>(
                            HID_H + row0 * NN + n0 + wn * 32 + col) = h0;
                if (vb) *reinterpret_cast<uint32_t*>(
                            HID_H + row1 * NN + n0 + wn * 32 + col) = h1;
            }
        } else {
            // fused combine: out[token] += gate * (acc + bias)
            float gate0 = 0.f, gate1 = 0.f;
            int tok0 = 0, tok1 = 0;
            if (va) { gate0 = __int_as_float(g_row[row0]); tok0 = g_tok[row0]; }
            if (vb) { gate1 = __int_as_float(g_row[row1]); tok1 = g_tok[row1]; }
            float* o0 = out + (size_t)tok0 * NN + n0 + wn * 32;
            float* o1 = out + (size_t)tok1 * NN + n0 + wn * 32;
#pragma unroll
            for (int ni = 0; ni < 4; ni++) {
                int col = ni * 8 + 2 * tg;
                float2 bv = *reinterpret_cast<const float2*>(bias + n0 + wn * 32 + col);
                if (va) {
                    atomicAdd(o0 + col,     gate0 * (acc[mi][ni][0] + bv.x));
                    atomicAdd(o0 + col + 1, gate0 * (acc[mi][ni][1] + bv.y));
                }
                if (vb) {
                    atomicAdd(o1 + col,     gate1 * (acc[mi][ni][2] + bv.x));
                    atomicAdd(o1 + col + 1, gate1 * (acc[mi][ni][3] + bv.y));
                }
            }
        }
    }
}

// ---------------- launch ----------------
extern "C" void kernel_launch(void* const* d_in, const int* in_sizes, int n_in,
                              void* d_out, int out_size) {
    const float* x  = (const float*)d_in[0];
    const float* wr = (const float*)d_in[1];
    const float* br = (const float*)d_in[2];
    const float* w1 = (const float*)d_in[3];
    const float* b1 = (const float*)d_in[4];
    const float* w2 = (const float*)d_in[5];
    const float* b2 = (const float*)d_in[6];
    float* out = (float*)d_out;

    cudaFuncSetAttribute(moe_gemm_h<HH, DD, true>,
                         cudaFuncAttributeMaxDynamicSharedMemorySize, GEMM_SMEM);
    cudaFuncSetAttribute(moe_gemm_h<DD, HH, false>,
                         cudaFuncAttributeMaxDynamicSharedMemorySize, GEMM_SMEM);

    zero_counts_kernel<<<1, 32>>>();
    zero_out_kernel<<<(T_TOKENS * DD / 4) / 256, 256>>>((float4*)out);
    router_kernel<<<T_TOKENS / 8, 256>>>(x, wr, br);   // also writes x fp16
    offsets_kernel<<<1, 32>>>();
    scatter_kernel<<<PAIRS / 256, 256>>>();

    // FFN1: N=4096, K=1024 (B from harness w1, converted in-kernel)
    {
        dim3 grid(HH / BN, 8192 / BM, EE);
        moe_gemm_h<HH, DD, true><<<grid, 256, GEMM_SMEM>>>(w1, b1, nullptr);
    }
    // FFN2: N=1024, K=4096; epilogue scatters gate*val into out via atomicAdd
    {
        dim3 grid(DD / BN, 8192 / BM, EE);
        moe_gemm_h<DD, HH, false><<<grid, 256, GEMM_SMEM>>>(w2, b2, out);
    }
}

// round 14
// speedup vs baseline: 1.2383x; 1.1472x over previous
#include <cuda_runtime.h>
#include <cuda_fp16.h>
#include <stdint.h>
#include <math.h>

// ---------------- problem constants ----------------
#define T_TOKENS 8192          // 4 * 2048
#define DD 1024                // emb dim
#define HH 4096                // hidden dim
#define EE 8                   // experts
#define PAIRS (T_TOKENS * 2)   // 16384 routed (token, expert) pairs

// ---------------- device scratch: proven footprint; NO weight copies ----------
__device__ int   g_count[EE];
__device__ int   g_ek[PAIRS];
__device__ int   g_slot[PAIRS];
__device__ float g_gate[PAIRS];
__device__ int   g_row[PAIRS];     // per (t,k): compact row id
__device__ int   g_tok[PAIRS];     // per compact row: token id
__device__ float g_hid[(size_t)PAIRS * HH];     // head 134 MB used as fp16 hid
__device__ float g_y  [(size_t)PAIRS * DD];     // head 16.7 MB = x fp16 alias

#define HID_H   (reinterpret_cast<__half*>(g_hid))
#define XH      (reinterpret_cast<__half*>(g_y))

// ---------------- helpers ----------------
__device__ __forceinline__ uint32_t smem_u32(const void* p) {
    uint32_t a;
    asm("{ .reg .u64 t; cvta.to.shared.u64 t, %1; cvt.u32.u64 %0, t; }" : "=r"(a) : "l"(p));
    return a;
}
__device__ __forceinline__ void cp_async16(uint32_t dst, const void* src) {
    asm volatile("cp.async.cg.shared.global [%0], [%1], 16;" :: "r"(dst), "l"(src));
}
__device__ __forceinline__ void cp_commit() {
    asm volatile("cp.async.commit_group;" ::: "memory");
}
template <int N>
__device__ __forceinline__ void cp_wait() {
    asm volatile("cp.async.wait_group %0;" :: "n"(N) : "memory");
}
__device__ __forceinline__ uint32_t pack_h2(float lo, float hi) {
    __half2 h = __floats2half2_rn(lo, hi);      // low 16 bits = lo
    return *reinterpret_cast<uint32_t*>(&h);
}
__device__ __forceinline__ void mma_f16(float* d, const uint32_t* a, const uint32_t* b) {
    asm volatile(
        "mma.sync.aligned.m16n8k16.row.col.f32.f16.f16.f32 "
        "{%0,%1,%2,%3}, {%4,%5,%6,%7}, {%8,%9}, {%0,%1,%2,%3};"
        : "+f"(d[0]), "+f"(d[1]), "+f"(d[2]), "+f"(d[3])
        : "r"(a[0]), "r"(a[1]), "r"(a[2]), "r"(a[3]), "r"(b[0]), "r"(b[1]));
}
__device__ __forceinline__ void ldsm_x4(uint32_t* r, uint32_t addr) {
    asm volatile("ldmatrix.sync.aligned.m8n8.x4.shared.b16 {%0,%1,%2,%3}, [%4];"
                 : "=r"(r[0]), "=r"(r[1]), "=r"(r[2]), "=r"(r[3]) : "r"(addr));
}
__device__ __forceinline__ int expert_offset(int e) {
    int s = 0;
#pragma unroll
    for (int i = 0; i < EE; i++) if (i < e) s += g_count[i];
    return s;
}

// ---------------- kernel 0: zero counters ----------------
__global__ void zero_counts_kernel() {
    if (threadIdx.x < EE) g_count[threadIdx.x] = 0;
}

// ---------------- kernel 1: router (1 warp/token) + fused x->fp16 ------------
__global__ void router_kernel(const float* __restrict__ x,
                              const float* __restrict__ wr,
                              const float* __restrict__ br) {
    int warp = (blockIdx.x * blockDim.x + threadIdx.x) >> 5;
    int lane = threadIdx.x & 31;
    if (warp >= T_TOKENS) return;
    const float* xr = x + (size_t)warp * DD;
    __half* xh = XH + (size_t)warp * DD;

    float acc[EE];
#pragma unroll
    for (int e = 0; e < EE; e++) acc[e] = 0.f;
#pragma unroll 4
    for (int c = 0; c < DD / 32; c++) {
        int k = c * 32 + lane;
        float xv = __ldg(xr + k);
        xh[k] = __float2half_rn(xv);             // fused fp16 conversion
        const float4* w4 = reinterpret_cast<const float4*>(wr + (size_t)k * EE);
        float4 a = __ldg(&w4[0]);
        float4 b = __ldg(&w4[1]);
        acc[0] += xv * a.x; acc[1] += xv * a.y; acc[2] += xv * a.z; acc[3] += xv * a.w;
        acc[4] += xv * b.x; acc[5] += xv * b.y; acc[6] += xv * b.z; acc[7] += xv * b.w;
    }
#pragma unroll
    for (int e = 0; e < EE; e++)
#pragma unroll
        for (int o = 16; o > 0; o >>= 1)
            acc[e] += __shfl_down_sync(0xffffffffu, acc[e], o);

    if (lane == 0) {
        float l[EE];
        float mx = -1e30f;
#pragma unroll
        for (int e = 0; e < EE; e++) { l[e] = acc[e] + br[e]; mx = fmaxf(mx, l[e]); }
        float s = 0.f;
#pragma unroll
        for (int e = 0; e < EE; e++) { l[e] = expf(l[e] - mx); s += l[e]; }
        float inv = 1.0f / s;
        int e0 = 0;
#pragma unroll
        for (int e = 1; e < EE; e++) if (l[e] > l[e0]) e0 = e;
        int e1 = (e0 == 0) ? 1 : 0;
#pragma unroll
        for (int e = 0; e < EE; e++) if (e != e0 && l[e] > l[e1]) e1 = e;
        int t = warp;
        int s0 = atomicAdd(&g_count[e0], 1);
        g_ek[t * 2 + 0] = e0; g_slot[t * 2 + 0] = s0; g_gate[t * 2 + 0] = l[e0] * inv;
        int s1 = atomicAdd(&g_count[e1], 1);
        g_ek[t * 2 + 1] = e1; g_slot[t * 2 + 1] = s1; g_gate[t * 2 + 1] = l[e1] * inv;
    }
}

// ---------------- kernel 2: scatter compact rows (offsets inline) ------------
__global__ void scatter_kernel() {
    int i = blockIdx.x * blockDim.x + threadIdx.x;
    if (i >= PAIRS) return;
    int e = g_ek[i];
    int row = expert_offset(e) + g_slot[i];
    g_row[i] = row;
    g_tok[row] = i >> 1;
}

// ---------------- grouped GEMM: m16n8k16 fp16 (R11 geometry + LDSM A frags) --
constexpr int BM = 128, BN = 128, BK = 32;   // BK in k-elements
constexpr int A_STR_U = 20;                  // 40 fp16 = 80 B row stride
constexpr int B_STR_U = 136;                 // u32 stride per k-pair row
constexpr int A_TILE_U = BM * A_STR_U;       // 2560 u32
constexpr int B_TILE_U = (BK / 2) * B_STR_U; // 2176 u32
constexpr int STAGE_U  = A_TILE_U + B_TILE_U;
constexpr int GEMM_SMEM = 2 * STAGE_U * 4;   // 37888 bytes

template <int NN, int KK, bool FFN1>
__global__ void __launch_bounds__(256, 2)
moe_gemm_h(const float* __restrict__ W_all,      // harness fp32 [E][K][N]
           const float* __restrict__ bias_all) {
    constexpr int NCH = KK / BK;
    extern __shared__ uint32_t smu[];
    uint32_t sb = smem_u32(smu);

    int e = blockIdx.z;
    int cnt = g_count[e];
    int m0 = blockIdx.y * BM;
    if (m0 >= cnt) return;
    int off = expert_offset(e);
    int n0 = blockIdx.x * BN;

    const float* W    = W_all + (size_t)e * KK * NN;
    const float* bias = bias_all + (size_t)e * NN;

    int tid = threadIdx.x;
    int wid = tid >> 5, lane = tid & 31;
    int wm = wid >> 2, wn = wid & 3;        // 2 x 4 warps; warp tile 64(m) x 32(n)
    int g = lane >> 2, tg = lane & 3;

    // ---- A: 2 gathered fp16 row pointers per thread ----
    const __half* asrc[2];
#pragma unroll
    for (int i = 0; i < 2; i++) {
        int r = i * 64 + (tid >> 2);
        int gm = m0 + r;
        if (gm > cnt - 1) gm = cnt - 1;     // clamp; masked in epilogue
        int grow = off + gm;
        const __half* base = FFN1 ? (XH + (size_t)g_tok[grow] * KK)
                                  : (HID_H + (size_t)grow * KK);
        asrc[i] = base + (tid & 3) * 8;
    }
    uint32_t adst0 = sb + (uint32_t)((tid >> 2) * 80 + (tid & 3) * 16);
    constexpr uint32_t STAGE_B = STAGE_U * 4;

    // ldmatrix A base: row = lane&15 within 16-row tile; k-half = lane>>4
    uint32_t a_lm = sb + (uint32_t)(((wm * 64 + (lane & 15)) * A_STR_U
                                     + (lane >> 4) * 4) * 4);

    // ---- B: per-thread LDG mapping. kpair row = tid/16, n = (tid%16)*4 + {0,64}
    int bkp = tid >> 4;
    int bn  = (tid & 15) * 4;
    const float* bw0 = W + (size_t)(2 * bkp)     * NN + n0 + bn;
    const float* bw1 = W + (size_t)(2 * bkp + 1) * NN + n0 + bn;
    uint32_t bst_off = (uint32_t)(A_TILE_U + bkp * B_STR_U + bn);

    float acc[4][4][4];
#pragma unroll
    for (int mi = 0; mi < 4; mi++)
#pragma unroll
        for (int ni = 0; ni < 4; ni++)
#pragma unroll
            for (int q = 0; q < 4; q++) acc[mi][ni][q] = 0.f;

    // ---- prologue: fill stage 0 (A cp.async; B ldg+cvt+sts) ----
#pragma unroll
    for (int i = 0; i < 2; i++) cp_async16(adst0 + i * (64 * 80), asrc[i]);
    cp_commit();
    {
        float4 v0 = *reinterpret_cast<const float4*>(bw0);
        float4 v1 = *reinterpret_cast<const float4*>(bw1);
        float4 u0 = *reinterpret_cast<const float4*>(bw0 + 64);
        float4 u1 = *reinterpret_cast<const float4*>(bw1 + 64);
        *reinterpret_cast<uint4*>(smu + bst_off) =
            make_uint4(pack_h2(v0.x, v1.x), pack_h2(v0.y, v1.y),
                       pack_h2(v0.z, v1.z), pack_h2(v0.w, v1.w));
        *reinterpret_cast<uint4*>(smu + bst_off + 64) =
            make_uint4(pack_h2(u0.x, u1.x), pack_h2(u0.y, u1.y),
                       pack_h2(u0.z, u1.z), pack_h2(u0.w, u1.w));
    }
    cp_wait<0>();
    __syncthreads();

#pragma unroll 1
    for (int c = 0; c < NCH; c++) {
        float4 v0, v1, u0, u1;
        bool pf = (c + 1 < NCH);
        uint32_t so = ((c + 1) & 1) * STAGE_B;
        uint32_t* bst = smu + ((c + 1) & 1) * STAGE_U + bst_off;
        size_t brow = (size_t)(c + 1) * BK * NN;
        if (pf) {
            int ka = (c + 1) * BK;
#pragma unroll
            for (int i = 0; i < 2; i++)
                cp_async16(adst0 + so + i * (64 * 80), asrc[i] + ka);
            cp_commit();
            v0 = *reinterpret_cast<const float4*>(bw0 + brow);
            v1 = *reinterpret_cast<const float4*>(bw1 + brow);
            u0 = *reinterpret_cast<const float4*>(bw0 + brow + 64);
            u1 = *reinterpret_cast<const float4*>(bw1 + brow + 64);
        }

        uint32_t a_stage = a_lm + (c & 1) * STAGE_B;
        const uint32_t* Bs = smu + (c & 1) * STAGE_U + A_TILE_U;
#pragma unroll
        for (int kh = 0; kh < 2; kh++) {         // two k=16 steps per BK=32
            uint32_t af[4][4], bf[4][2];
#pragma unroll
            for (int mi = 0; mi < 4; mi++)       // ldmatrix x4: a0..a3 in mma order
                ldsm_x4(af[mi], a_stage + (uint32_t)((mi * 16 * A_STR_U + kh * 8) * 4));
#pragma unroll
            for (int ni = 0; ni < 4; ni++) {
                const uint32_t* bp = Bs + (kh * 8 + tg) * B_STR_U + wn * 32 + ni * 8 + g;
                bf[ni][0] = bp[0];
                bf[ni][1] = bp[4 * B_STR_U];
            }
#pragma unroll
            for (int mi = 0; mi < 4; mi++)
#pragma unroll
                for (int ni = 0; ni < 4; ni++)
                    mma_f16(acc[mi][ni], af[mi], bf[ni]);
        }

        if (pf) {
            *reinterpret_cast<uint4*>(bst) =
                make_uint4(pack_h2(v0.x, v1.x), pack_h2(v0.y, v1.y),
                           pack_h2(v0.z, v1.z), pack_h2(v0.w, v1.w));
            *reinterpret_cast<uint4*>(bst + 64) =
                make_uint4(pack_h2(u0.x, u1.x), pack_h2(u0.y, u1.y),
                           pack_h2(u0.z, u1.z), pack_h2(u0.w, u1.w));
            cp_wait<0>();
        }
        __syncthreads();
    }

    // ---- epilogue ----
#pragma unroll
    for (int mi = 0; mi < 4; mi++) {
        int r0 = m0 + wm * 64 + mi * 16 + g;
        int r1 = r0 + 8;
        bool va = r0 < cnt, vb = r1 < cnt;
        size_t row0 = (size_t)(off + r0), row1 = (size_t)(off + r1);
#pragma unroll
        for (int ni = 0; ni < 4; ni++) {
            int col = ni * 8 + 2 * tg;
            float2 bv = *reinterpret_cast<const float2*>(bias + n0 + wn * 32 + col);
            float c00 = acc[mi][ni][0] + bv.x;
            float c01 = acc[mi][ni][1] + bv.y;
            float c10 = acc[mi][ni][2] + bv.x;
            float c11 = acc[mi][ni][3] + bv.y;
            if (FFN1) {
                uint32_t h0 = pack_h2(fmaxf(c00, 0.f), fmaxf(c01, 0.f));
                uint32_t h1 = pack_h2(fmaxf(c10, 0.f), fmaxf(c11, 0.f));
                if (va) *reinterpret_cast<uint32_t*>(
                            HID_H + row0 * NN + n0 + wn * 32 + col) = h0;
                if (vb) *reinterpret_cast<uint32_t*>(
                            HID_H + row1 * NN + n0 + wn * 32 + col) = h1;
            } else {
                if (va) *reinterpret_cast<float2*>(
                            g_y + row0 * NN + n0 + wn * 32 + col) = make_float2(c00, c01);
                if (vb) *reinterpret_cast<float2*>(
                            g_y + row1 * NN + n0 + wn * 32 + col) = make_float2(c10, c11);
            }
        }
    }
}

// ---------------- combine pairs into output ----------------
__global__ void combine_kernel(float* __restrict__ out) {
    int i = blockIdx.x * blockDim.x + threadIdx.x;
    if (i >= T_TOKENS * (DD / 4)) return;
    int t  = i / (DD / 4);
    int d4 = i % (DD / 4);
    int r0 = g_row[t * 2 + 0];
    int r1 = g_row[t * 2 + 1];
    float g0 = g_gate[t * 2 + 0];
    float g1 = g_gate[t * 2 + 1];
    const float4* y0 = reinterpret_cast<const float4*>(g_y + (size_t)r0 * DD);
    const float4* y1 = reinterpret_cast<const float4*>(g_y + (size_t)r1 * DD);
    float4 a = y0[d4], b = y1[d4], o;
    o.x = g0 * a.x + g1 * b.x;
    o.y = g0 * a.y + g1 * b.y;
    o.z = g0 * a.z + g1 * b.z;
    o.w = g0 * a.w + g1 * b.w;
    reinterpret_cast<float4*>(out)[i] = o;
}

// ---------------- launch ----------------
extern "C" void kernel_launch(void* const* d_in, const int* in_sizes, int n_in,
                              void* d_out, int out_size) {
    const float* x  = (const float*)d_in[0];
    const float* wr = (const float*)d_in[1];
    const float* br = (const float*)d_in[2];
    const float* w1 = (const float*)d_in[3];
    const float* b1 = (const float*)d_in[4];
    const float* w2 = (const float*)d_in[5];
    const float* b2 = (const float*)d_in[6];
    float* out = (float*)d_out;

    cudaFuncSetAttribute(moe_gemm_h<HH, DD, true>,
                         cudaFuncAttributeMaxDynamicSharedMemorySize, GEMM_SMEM);
    cudaFuncSetAttribute(moe_gemm_h<DD, HH, false>,
                         cudaFuncAttributeMaxDynamicSharedMemorySize, GEMM_SMEM);

    zero_counts_kernel<<<1, 32>>>();
    router_kernel<<<T_TOKENS / 8, 256>>>(x, wr, br);   // also writes x fp16
    scatter_kernel<<<PAIRS / 256, 256>>>();

    // FFN1: N=4096, K=1024 (B from harness w1, converted in-kernel)
    {
        dim3 grid(HH / BN, 8192 / BM, EE);
        moe_gemm_h<HH, DD, true><<<grid, 256, GEMM_SMEM>>>(w1, b1);
    }
    // FFN2: N=1024, K=4096 (B from harness w2)
    {
        dim3 grid(DD / BN, 8192 / BM, EE);
        moe_gemm_h<DD, HH, false><<<grid, 256, GEMM_SMEM>>>(w2, b2);
    }

    combine_kernel<<<(T_TOKENS * (DD / 4)) / 256, 256>>>(out);
}